// round 3
// baseline (speedup 1.0000x reference)
#include <cuda_runtime.h>
#include <math.h>

#define BB  4
#define CC  256
#define ACK 64      // attn channels
#define NN  4096    // W*H

// -------- device-global scratch (no runtime allocation allowed) --------
__device__ float g_v[(size_t)BB * CC * NN];            //  16 MB  [b][c][j]
__device__ float g_P[(size_t)BB * NN * NN];            // 256 MB  [b][j][i]  probs, transposed

// ---------------------------------------------------------------------
// Kernel A (heavy path only; early-exits when gamma==0):
// For each (b, j-tile of 32 key columns):
//   - recompute k[64][32] and v[256][32] from x (v written to g_v)
//   - loop i-tiles: recompute q[64][32] from x, compute scores,
//     write raw scores to g_P[b][j][i], track per-row max
//   - pass 2: exp + row sum over the (L2-hot) written row
//   - pass 3: scale by 1/sum  -> g_P holds softmax(axis=i) probabilities
// ---------------------------------------------------------------------
__global__ void fused_ps_kernel(const float* __restrict__ x,
                                const float* __restrict__ Wq, const float* __restrict__ bq,
                                const float* __restrict__ Wk, const float* __restrict__ bk,
                                const float* __restrict__ Wv, const float* __restrict__ bv,
                                const float* __restrict__ gamma)
{
    if (gamma[0] == 0.0f) return;   // gamma*A + x == x : all attention work dead

    __shared__ float xs[128][32];   // 16 KB : half of channels of one 32-col slab
    __shared__ float kt[ACK][32];   //  8 KB
    __shared__ float qt[ACK][32];   //  8 KB
    __shared__ float rowmax[32];
    __shared__ float rowsum[32];

    const int t    = threadIdx.x;
    const int tx   = t & 31;
    const int wid  = t >> 5;        // 0..7
    const int c64  = t & 63;
    const int part = t >> 6;        // 0..3

    const int ntiles = BB * (NN / 32);   // 512
    for (int tile = blockIdx.x; tile < ntiles; tile += gridDim.x) {
        int b  = tile >> 7;
        int jt = tile & 127;
        int j0 = jt * 32;
        const float* xb = x + (size_t)b * CC * NN;
        float* Pb = g_P + (size_t)b * NN * NN;

        // ---- k tile + v tile from x columns [j0, j0+32) ----
        float vacc[32];
        #pragma unroll
        for (int u = 0; u < 32; u++) vacc[u] = bv[t];
        float kacc[8];
        #pragma unroll
        for (int u = 0; u < 8; u++) kacc[u] = bk[c64];

        for (int half = 0; half < 2; half++) {
            __syncthreads();
            for (int r = wid; r < 128; r += 8)
                xs[r][tx] = xb[(size_t)(half * 128 + r) * NN + j0 + tx];
            __syncthreads();
            for (int r = 0; r < 128; r++) {
                float wv = Wv[(size_t)t * CC + half * 128 + r];
                #pragma unroll 8
                for (int u = 0; u < 32; u++) vacc[u] += wv * xs[r][u];
                float wk = Wk[(size_t)c64 * CC + half * 128 + r];
                #pragma unroll
                for (int u = 0; u < 8; u++) kacc[u] += wk * xs[r][part * 8 + u];
            }
        }
        {
            float* vdst = g_v + ((size_t)b * CC + t) * NN + j0;
            #pragma unroll 8
            for (int u = 0; u < 32; u++) vdst[u] = vacc[u];
        }
        #pragma unroll
        for (int u = 0; u < 8; u++) kt[c64][part * 8 + u] = kacc[u];
        if (t < 32) rowmax[t] = -INFINITY;
        __syncthreads();

        // ---- i-loop: q tile, scores, raw write, running row max ----
        for (int it = 0; it < 128; it++) {
            int i0 = it * 32;
            float qacc[8];
            #pragma unroll
            for (int u = 0; u < 8; u++) qacc[u] = bq[c64];
            for (int half = 0; half < 2; half++) {
                __syncthreads();   // previous users of xs / qt done
                for (int r = wid; r < 128; r += 8)
                    xs[r][tx] = xb[(size_t)(half * 128 + r) * NN + i0 + tx];
                __syncthreads();
                for (int r = 0; r < 128; r++) {
                    float wq = Wq[(size_t)c64 * CC + half * 128 + r];
                    #pragma unroll
                    for (int u = 0; u < 8; u++) qacc[u] += wq * xs[r][part * 8 + u];
                }
            }
            #pragma unroll
            for (int u = 0; u < 8; u++) qt[c64][part * 8 + u] = qacc[u];
            __syncthreads();

            float s[4] = {0.f, 0.f, 0.f, 0.f};
            for (int c = 0; c < ACK; c++) {
                float qv = qt[c][tx];
                #pragma unroll
                for (int ss = 0; ss < 4; ss++) s[ss] += qv * kt[c][wid + 8 * ss];
            }
            #pragma unroll
            for (int ss = 0; ss < 4; ss++) {
                int jj = wid + 8 * ss;        // exclusive row ownership per warp
                Pb[(size_t)(j0 + jj) * NN + i0 + tx] = s[ss];
                float m = s[ss];
                for (int o = 16; o > 0; o >>= 1)
                    m = fmaxf(m, __shfl_xor_sync(0xffffffffu, m, o));
                if (tx == 0) rowmax[jj] = fmaxf(rowmax[jj], m);
            }
        }
        __syncthreads();

        // ---- pass 2: exp + row sum (rows just written; L2-hot) ----
        #pragma unroll
        for (int ss = 0; ss < 4; ss++) {
            int jj = wid + 8 * ss;
            float m = rowmax[jj];
            float* row = Pb + (size_t)(j0 + jj) * NN;
            float sum = 0.f;
            for (int i = tx; i < NN; i += 32) {
                float e = expf(row[i] - m);
                row[i] = e;
                sum += e;
            }
            for (int o = 16; o > 0; o >>= 1)
                sum += __shfl_xor_sync(0xffffffffu, sum, o);
            if (tx == 0) rowsum[jj] = sum;
        }
        __syncthreads();

        // ---- pass 3: normalize ----
        #pragma unroll
        for (int ss = 0; ss < 4; ss++) {
            int jj = wid + 8 * ss;
            float inv = 1.0f / rowsum[jj];
            float* row = Pb + (size_t)(j0 + jj) * NN;
            for (int i = tx; i < NN; i += 32) row[i] *= inv;
        }
        __syncthreads();
    }
}

// ---------------------------------------------------------------------
// Kernel B (heavy path only; early-exits when gamma==0):
// out[b,c,i] = gamma * sum_j P[b,j,i] * v[b,c,j] + x[b,c,i]
// The gamma==0 case is fully handled by the memcpy node (out = x).
// ---------------------------------------------------------------------
__global__ void out_kernel(const float* __restrict__ x,
                           const float* __restrict__ gamma,
                           float* __restrict__ out)
{
    float g = gamma[0];
    if (g == 0.0f) return;   // memcpy already produced out = x

    __shared__ float vs[32][32];
    __shared__ float ps[32][33];
    const int tilesC = CC / 32, tilesI = NN / 32;
    const int ntiles = BB * tilesC * tilesI;          // 4096
    int tx = threadIdx.x & 31, ty = threadIdx.x >> 5;
    for (int t = blockIdx.x; t < ntiles; t += gridDim.x) {
        int b  = t / (tilesC * tilesI);
        int rr = t % (tilesC * tilesI);
        int ct = rr / tilesI, it = rr % tilesI;
        int c0 = ct * 32, i0 = it * 32;
        float acc[4] = {0.f, 0.f, 0.f, 0.f};
        for (int j0 = 0; j0 < NN; j0 += 32) {
            for (int rl = ty; rl < 32; rl += 8) {
                vs[rl][tx] = g_v[((size_t)b * CC + c0 + rl) * NN + j0 + tx];
                ps[rl][tx] = g_P[((size_t)b * NN + j0 + rl) * NN + i0 + tx];
            }
            __syncthreads();
            #pragma unroll
            for (int jj = 0; jj < 32; jj++) {
                float pv = ps[jj][tx];
                #pragma unroll
                for (int s = 0; s < 4; s++) acc[s] += vs[ty + 8 * s][jj] * pv;
            }
            __syncthreads();
        }
        #pragma unroll
        for (int s = 0; s < 4; s++) {
            size_t oidx = ((size_t)b * CC + c0 + ty + 8 * s) * NN + i0 + tx;
            out[oidx] = g * acc[s] + x[oidx];
        }
    }
}

// ---------------------------------------------------------------------
extern "C" void kernel_launch(void* const* d_in, const int* in_sizes, int n_in,
                              void* d_out, int out_size)
{
    const float* x     = (const float*)d_in[0];
    const float* Wq    = (const float*)d_in[1];
    const float* bq    = (const float*)d_in[2];
    const float* Wk    = (const float*)d_in[3];
    const float* bk    = (const float*)d_in[4];
    const float* Wv    = (const float*)d_in[5];
    const float* bv    = (const float*)d_in[6];
    const float* gamma = (const float*)d_in[7];
    float* out = (float*)d_out;

    // Unconditional out = x. When gamma==0 this IS the final answer;
    // when gamma!=0, out_kernel fully overwrites out afterwards
    // (same-stream ordering), so this is always correct.
    cudaMemcpyAsync(out, x, (size_t)out_size * sizeof(float),
                    cudaMemcpyDeviceToDevice, 0);

    fused_ps_kernel<<<512, 256>>>(x, Wq, bq, Wk, bk, Wv, bv, gamma);
    out_kernel     <<<1024, 256>>>(x, gamma, out);
}

// round 4
// speedup vs baseline: 1.2362x; 1.2362x over previous
#include <cuda_runtime.h>
#include <math.h>

#define BB  4
#define CC  256
#define ACK 64      // attn channels
#define NN  4096    // W*H
#define GRID 148    // one CTA per SM -> single wave, safe spin barrier

// -------- device-global scratch (no runtime allocation allowed) --------
__device__ float g_v[(size_t)BB * CC * NN];            //  16 MB  [b][c][j]
__device__ float g_P[(size_t)BB * NN * NN];            // 256 MB  [b][j][i]  probs, transposed
__device__ unsigned g_bar_count = 0;
__device__ unsigned g_bar_sense = 0;

// Software grid barrier. Valid because grid==148 <= #SMs and the kernel fits
// one CTA/SM, so all CTAs are co-resident. Sense is read fresh per launch;
// count returns to 0 -> deterministic across graph replays.
__device__ __forceinline__ void grid_sync()
{
    __syncthreads();
    __threadfence();
    if (threadIdx.x == 0) {
        unsigned s = atomicAdd(&g_bar_sense, 0u);     // read current sense
        unsigned old = atomicAdd(&g_bar_count, 1u);
        if (old == GRID - 1) {
            atomicExch(&g_bar_count, 0u);
            __threadfence();
            atomicExch(&g_bar_sense, s ^ 1u);
        } else {
            while (atomicAdd(&g_bar_sense, 0u) == s) { }
        }
    }
    __syncthreads();
}

// ---------------------------------------------------------------------
// ONE kernel, heavy path only (early-exits when gamma==0):
// Phase 1: per (b, j-tile): recompute k,v from x (v -> g_v), loop i-tiles
//          recomputing q, write scores to g_P[b][j][i], softmax over i.
// grid_sync()
// Phase 2: out[b,c,i] = gamma * sum_j P[b,j,i]*v[b,c,j] + x[b,c,i]
//          (memcpy node already wrote out = x for the gamma==0 case).
// ---------------------------------------------------------------------
__global__ void __launch_bounds__(256, 1)
attn_kernel(const float* __restrict__ x,
            const float* __restrict__ Wq, const float* __restrict__ bq,
            const float* __restrict__ Wk, const float* __restrict__ bk,
            const float* __restrict__ Wv, const float* __restrict__ bv,
            const float* __restrict__ gamma,
            float* __restrict__ out)
{
    const float g = gamma[0];
    if (g == 0.0f) return;   // out = x already produced by the memcpy node

    __shared__ float xs[128][32];   // 16 KB
    __shared__ float kt[ACK][32];   //  8 KB
    __shared__ float qt[ACK][32];   //  8 KB
    __shared__ float rowmax[32];
    __shared__ float rowsum[32];
    __shared__ float vs[32][32];    //  4 KB   (phase 2)
    __shared__ float ps[32][33];    //  4.1 KB (phase 2)

    const int t    = threadIdx.x;
    const int tx   = t & 31;
    const int wid  = t >> 5;        // 0..7
    const int c64  = t & 63;
    const int part = t >> 6;        // 0..3

    // ================= Phase 1: P (softmaxed, transposed) + v =================
    const int ntiles1 = BB * (NN / 32);   // 512
    for (int tile = blockIdx.x; tile < ntiles1; tile += GRID) {
        int b  = tile >> 7;
        int jt = tile & 127;
        int j0 = jt * 32;
        const float* xb = x + (size_t)b * CC * NN;
        float* Pb = g_P + (size_t)b * NN * NN;

        // ---- k tile + v tile from x columns [j0, j0+32) ----
        float vacc[32];
        #pragma unroll
        for (int u = 0; u < 32; u++) vacc[u] = bv[t];
        float kacc[8];
        #pragma unroll
        for (int u = 0; u < 8; u++) kacc[u] = bk[c64];

        for (int half = 0; half < 2; half++) {
            __syncthreads();
            for (int r = wid; r < 128; r += 8)
                xs[r][tx] = xb[(size_t)(half * 128 + r) * NN + j0 + tx];
            __syncthreads();
            for (int r = 0; r < 128; r++) {
                float wv = Wv[(size_t)t * CC + half * 128 + r];
                #pragma unroll 8
                for (int u = 0; u < 32; u++) vacc[u] += wv * xs[r][u];
                float wk = Wk[(size_t)c64 * CC + half * 128 + r];
                #pragma unroll
                for (int u = 0; u < 8; u++) kacc[u] += wk * xs[r][part * 8 + u];
            }
        }
        {
            float* vdst = g_v + ((size_t)b * CC + t) * NN + j0;
            #pragma unroll 8
            for (int u = 0; u < 32; u++) vdst[u] = vacc[u];
        }
        #pragma unroll
        for (int u = 0; u < 8; u++) kt[c64][part * 8 + u] = kacc[u];
        if (t < 32) rowmax[t] = -INFINITY;
        __syncthreads();

        // ---- i-loop: q tile, scores, raw write, running row max ----
        for (int it = 0; it < 128; it++) {
            int i0 = it * 32;
            float qacc[8];
            #pragma unroll
            for (int u = 0; u < 8; u++) qacc[u] = bq[c64];
            for (int half = 0; half < 2; half++) {
                __syncthreads();
                for (int r = wid; r < 128; r += 8)
                    xs[r][tx] = xb[(size_t)(half * 128 + r) * NN + i0 + tx];
                __syncthreads();
                for (int r = 0; r < 128; r++) {
                    float wq = Wq[(size_t)c64 * CC + half * 128 + r];
                    #pragma unroll
                    for (int u = 0; u < 8; u++) qacc[u] += wq * xs[r][part * 8 + u];
                }
            }
            #pragma unroll
            for (int u = 0; u < 8; u++) qt[c64][part * 8 + u] = qacc[u];
            __syncthreads();

            float s[4] = {0.f, 0.f, 0.f, 0.f};
            for (int c = 0; c < ACK; c++) {
                float qv = qt[c][tx];
                #pragma unroll
                for (int ss = 0; ss < 4; ss++) s[ss] += qv * kt[c][wid + 8 * ss];
            }
            #pragma unroll
            for (int ss = 0; ss < 4; ss++) {
                int jj = wid + 8 * ss;        // exclusive row ownership per warp
                Pb[(size_t)(j0 + jj) * NN + i0 + tx] = s[ss];
                float m = s[ss];
                for (int o = 16; o > 0; o >>= 1)
                    m = fmaxf(m, __shfl_xor_sync(0xffffffffu, m, o));
                if (tx == 0) rowmax[jj] = fmaxf(rowmax[jj], m);
            }
        }
        __syncthreads();

        // ---- pass 2: exp + row sum (rows just written; L2-hot) ----
        #pragma unroll
        for (int ss = 0; ss < 4; ss++) {
            int jj = wid + 8 * ss;
            float m = rowmax[jj];
            float* row = Pb + (size_t)(j0 + jj) * NN;
            float sum = 0.f;
            for (int i = tx; i < NN; i += 32) {
                float e = expf(row[i] - m);
                row[i] = e;
                sum += e;
            }
            for (int o = 16; o > 0; o >>= 1)
                sum += __shfl_xor_sync(0xffffffffu, sum, o);
            if (tx == 0) rowsum[jj] = sum;
        }
        __syncthreads();

        // ---- pass 3: normalize ----
        #pragma unroll
        for (int ss = 0; ss < 4; ss++) {
            int jj = wid + 8 * ss;
            float inv = 1.0f / rowsum[jj];
            float* row = Pb + (size_t)(j0 + jj) * NN;
            for (int i = tx; i < NN; i += 32) row[i] *= inv;
        }
        __syncthreads();
    }

    // ================= grid-wide barrier =================
    grid_sync();

    // ================= Phase 2: out GEMM + residual =================
    const int tilesC = CC / 32, tilesI = NN / 32;
    const int ntiles2 = BB * tilesC * tilesI;          // 4096
    for (int tile = blockIdx.x; tile < ntiles2; tile += GRID) {
        int b  = tile / (tilesC * tilesI);
        int rr = tile % (tilesC * tilesI);
        int ct = rr / tilesI, it = rr % tilesI;
        int c0 = ct * 32, i0 = it * 32;
        float acc[4] = {0.f, 0.f, 0.f, 0.f};
        for (int j0 = 0; j0 < NN; j0 += 32) {
            for (int rl = wid; rl < 32; rl += 8) {
                vs[rl][tx] = g_v[((size_t)b * CC + c0 + rl) * NN + j0 + tx];
                ps[rl][tx] = g_P[((size_t)b * NN + j0 + rl) * NN + i0 + tx];
            }
            __syncthreads();
            #pragma unroll
            for (int jj = 0; jj < 32; jj++) {
                float pv = ps[jj][tx];
                #pragma unroll
                for (int s = 0; s < 4; s++) acc[s] += vs[wid + 8 * s][jj] * pv;
            }
            __syncthreads();
        }
        #pragma unroll
        for (int s = 0; s < 4; s++) {
            size_t oidx = ((size_t)b * CC + c0 + wid + 8 * s) * NN + i0 + tx;
            out[oidx] = g * acc[s] + x[oidx];
        }
    }
}

// ---------------------------------------------------------------------
extern "C" void kernel_launch(void* const* d_in, const int* in_sizes, int n_in,
                              void* d_out, int out_size)
{
    const float* x     = (const float*)d_in[0];
    const float* Wq    = (const float*)d_in[1];
    const float* bq    = (const float*)d_in[2];
    const float* Wk    = (const float*)d_in[3];
    const float* bk    = (const float*)d_in[4];
    const float* Wv    = (const float*)d_in[5];
    const float* bv    = (const float*)d_in[6];
    const float* gamma = (const float*)d_in[7];
    float* out = (float*)d_out;

    // Unconditional out = x via copy engine. When gamma==0 this IS the final
    // answer; when gamma!=0 the kernel fully overwrites out afterwards
    // (same-stream ordering), so this is always correct.
    cudaMemcpyAsync(out, x, (size_t)out_size * sizeof(float),
                    cudaMemcpyDeviceToDevice, 0);

    attn_kernel<<<GRID, 256>>>(x, Wq, bq, Wk, bk, Wv, bv, gamma, out);
}